// round 16
// baseline (speedup 1.0000x reference)
#include <cuda_runtime.h>

#define BB   8
#define NN   4096
#define DIN  128
#define DOUT 256
#define SS   1024
#define KKNN 16
#define MTOT (BB*SS*KKNN)
#define XYZ_OFF (BB*SS*DOUT)

__device__ float  g_h[BB*NN*DOUT];      // h for all points (33.5MB, L2-resident)
__device__ float  g_hmax[BB*SS*DOUT];   // per-sample max over K (8MB)
__device__ int    g_knn[MTOT];
__device__ float  g_psum[512*DOUT];
__device__ float  g_psumsq[512*DOUT];
__device__ float  g_fsum[DOUT];
__device__ float  g_fsumsq[DOUT];
__device__ unsigned g_prog[BB];         // FPS progress per batch (samples done)

// ---- f32x2 packed helpers: per-element round-to-nearest == scalar RN ----
__device__ __forceinline__ unsigned long long pk2(float lo, float hi) {
    unsigned long long r;
    asm("mov.b64 %0, {%1, %2};" : "=l"(r) : "f"(lo), "f"(hi));
    return r;
}
__device__ __forceinline__ void upk2(unsigned long long v, float& lo, float& hi) {
    asm("mov.b64 {%0, %1}, %2;" : "=f"(lo), "=f"(hi) : "l"(v));
}
__device__ __forceinline__ unsigned long long add2(unsigned long long a, unsigned long long b) {
    unsigned long long r;
    asm("add.rn.f32x2 %0, %1, %2;" : "=l"(r) : "l"(a), "l"(b));
    return r;
}
__device__ __forceinline__ unsigned long long mul2(unsigned long long a, unsigned long long b) {
    unsigned long long r;
    asm("mul.rn.f32x2 %0, %1, %2;" : "=l"(r) : "l"(a), "l"(b));
    return r;
}

// zero progress counters (graph-replay safe) — also serves as ncu window pad
__global__ void k0_zero() { if (threadIdx.x < BB) g_prog[threadIdx.x] = 0u; }
__global__ void k0_nop() {}

// ---------------------------------------------------------------------------
// FUSED kernel: bid 0..7 FPS (publishes progress), 8..519 SGEMM, 520..647 KNN
// (spins on progress, processes its 64-query chunk as soon as available).
// ---------------------------------------------------------------------------
__global__ __launch_bounds__(1024) void k1_fused(
    const float* __restrict__ feat, const float* __restrict__ xyz,
    const float* __restrict__ W, const float* __restrict__ bias,
    float* __restrict__ out)
{
    extern __shared__ float sm[];
    const int tid = threadIdx.x;
    const int bid = blockIdx.x;

    if (bid < BB) {
        // ================= FPS (bit-frozen selection math) =================
        float* sx = sm;  float* sy = sm + NN;  float* sz = sm + 2*NN;
        unsigned long long* wpack = (unsigned long long*)(sm + 3*NN); // [2][32]

        const float* bx = xyz + (size_t)bid * NN * 3;
        float px[4], py[4], pz[4];
        #pragma unroll
        for (int j = 0; j < 4; j++) {
            int i = j*1024 + tid;
            float x = bx[i*3+0], y = bx[i*3+1], z = bx[i*3+2];
            px[j]=x; py[j]=y; pz[j]=z;
            sx[i]=x; sy[i]=y; sz[i]=z;
        }
        const unsigned long long pX01 = pk2(px[0], px[1]), pX23 = pk2(px[2], px[3]);
        const unsigned long long pY01 = pk2(py[0], py[1]), pY23 = pk2(py[2], py[3]);
        const unsigned long long pZ01 = pk2(pz[0], pz[1]), pZ23 = pk2(pz[2], pz[3]);
        const unsigned INIT = __float_as_uint(1e10f);
        unsigned du0=INIT, du1=INIT, du2=INIT, du3=INIT;
        __syncthreads();
        float lx = sx[0], ly = sy[0], lz = sz[0];
        if (tid == 0) {
            float* o = out + XYZ_OFF + (size_t)(bid*SS)*3;
            o[0]=lx; o[1]=ly; o[2]=lz;
        }
        const unsigned rb = 4095u - (unsigned)tid;
        const int lane = tid & 31, wid = tid >> 5;

        for (int s = 1; s < SS; s++) {
            float nlx = __uint_as_float(__float_as_uint(lx) ^ 0x80000000u);
            float nly = __uint_as_float(__float_as_uint(ly) ^ 0x80000000u);
            float nlz = __uint_as_float(__float_as_uint(lz) ^ 0x80000000u);
            unsigned long long Lx = pk2(nlx, nlx), Ly = pk2(nly, nly), Lz = pk2(nlz, nlz);

            unsigned long long dxA = add2(pX01, Lx), dyA = add2(pY01, Ly), dzA = add2(pZ01, Lz);
            unsigned long long sA  = add2(add2(mul2(dxA,dxA), mul2(dyA,dyA)), mul2(dzA,dzA));
            unsigned long long dxB = add2(pX23, Lx), dyB = add2(pY23, Ly), dzB = add2(pZ23, Lz);
            unsigned long long sB  = add2(add2(mul2(dxB,dxB), mul2(dyB,dyB)), mul2(dzB,dzB));
            float d0,d1,d2,d3;
            upk2(sA, d0, d1);  upk2(sB, d2, d3);
            du0 = min(du0, __float_as_uint(d0));
            du1 = min(du1, __float_as_uint(d1));
            du2 = min(du2, __float_as_uint(d2));
            du3 = min(du3, __float_as_uint(d3));
            unsigned b01 = max(du0, du1);  unsigned r01 = (du0 >= du1) ? rb           : (rb - 1024u);
            unsigned b23 = max(du2, du3);  unsigned r23 = (du2 >= du3) ? (rb - 2048u) : (rb - 3072u);
            unsigned bv  = max(b01, b23);  unsigned rr  = (b01 >= b23) ? r01 : r23;
            unsigned m    = __reduce_max_sync(0xffffffffu, bv);
            unsigned rwin = __reduce_max_sync(0xffffffffu, (bv == m) ? rr : 0u);
            const int buf = (s & 1) << 5;
            if (lane == 0) wpack[buf + wid] = ((unsigned long long)m << 32) | rwin;
            __syncthreads();
            unsigned long long pkv = wpack[buf + lane];
            unsigned v  = (unsigned)(pkv >> 32);
            unsigned r2 = (unsigned)pkv;
            unsigned m2 = __reduce_max_sync(0xffffffffu, v);
            unsigned rw = __reduce_max_sync(0xffffffffu, (v == m2) ? r2 : 0u);
            unsigned w  = 4095u - rw;
            lx = sx[w]; ly = sy[w]; lz = sz[w];
            if (tid == 0) {
                float* o = out + XYZ_OFF + (size_t)(bid*SS + s)*3;
                o[0]=lx; o[1]=ly; o[2]=lz;
                if ((s & 63) == 63) {
                    __threadfence();
                    atomicExch(&g_prog[bid], (unsigned)(s + 1));
                }
            }
        }
    } else if (bid < BB + 512) {
        // ================= SGEMM: h = feat @ W^T + b, exact fp32 ===========
        const int g = bid - BB;
        const int rowBase = (g & 255) * 128;
        const int colBase = (g >> 8) * 128;
        float* As = sm;              // [16][132]
        float* Bs = sm + 16*132;     // [16][132]
        const int l = tid & 31, w = tid >> 5;
        const int tm = l*4, tn = w*4;
        float acc[4][4];
        #pragma unroll
        for (int i=0;i<4;i++)
            #pragma unroll
            for (int j=0;j<4;j++) acc[i][j] = 0.f;

        for (int kc = 0; kc < DIN; kc += 16) {
            if (tid < 512) {
                int r = tid >> 2, q = tid & 3;
                float4 v = *(const float4*)(feat + (size_t)(rowBase + r)*DIN + kc + q*4);
                As[(q*4+0)*132 + r] = v.x;
                As[(q*4+1)*132 + r] = v.y;
                As[(q*4+2)*132 + r] = v.z;
                As[(q*4+3)*132 + r] = v.w;
            } else {
                int t2 = tid - 512; int c = t2 >> 2, q = t2 & 3;
                float4 v = *(const float4*)(W + (size_t)(colBase + c)*DIN + kc + q*4);
                Bs[(q*4+0)*132 + c] = v.x;
                Bs[(q*4+1)*132 + c] = v.y;
                Bs[(q*4+2)*132 + c] = v.z;
                Bs[(q*4+3)*132 + c] = v.w;
            }
            __syncthreads();
            #pragma unroll
            for (int kk = 0; kk < 16; kk++) {
                float4 a  = *(const float4*)(As + kk*132 + tm);
                float4 bb = *(const float4*)(Bs + kk*132 + tn);
                acc[0][0] += a.x*bb.x; acc[0][1] += a.x*bb.y; acc[0][2] += a.x*bb.z; acc[0][3] += a.x*bb.w;
                acc[1][0] += a.y*bb.x; acc[1][1] += a.y*bb.y; acc[1][2] += a.y*bb.z; acc[1][3] += a.y*bb.w;
                acc[2][0] += a.z*bb.x; acc[2][1] += a.z*bb.y; acc[2][2] += a.z*bb.z; acc[2][3] += a.z*bb.w;
                acc[3][0] += a.w*bb.x; acc[3][1] += a.w*bb.y; acc[3][2] += a.w*bb.z; acc[3][3] += a.w*bb.w;
            }
            __syncthreads();
        }
        #pragma unroll
        for (int i = 0; i < 4; i++) {
            int row = rowBase + tm + i;
            float4 o;
            o.x = acc[i][0] + bias[colBase+tn+0];
            o.y = acc[i][1] + bias[colBase+tn+1];
            o.z = acc[i][2] + bias[colBase+tn+2];
            o.w = acc[i][3] + bias[colBase+tn+3];
            *(float4*)(g_h + (size_t)row*DOUT + colBase + tn) = o;
        }
    } else {
        // ================= KNN: one 64-query chunk per block ================
        const int kb = bid - (BB + 512);   // 0..127
        const int b = kb >> 4;             // batch
        const int chunk = kb & 15;         // 64-query chunk
        if (tid == 0) {
            const unsigned target = (unsigned)((chunk + 1) * 64);
            while (__ldcg(&g_prog[b]) < target) __nanosleep(128);
        }
        __syncthreads();
        __threadfence();

        float4* s4 = (float4*)sm;                                       // [NN] 64KB
        unsigned long long* ent = (unsigned long long*)(sm + 4*NN);     // [64*256] 128KB
        ulonglong2* t16 = (ulonglong2*)(ent + 64*256);                  // [64][16] 16KB

        const float* bx = xyz + (size_t)b * NN * 3;
        for (int i = tid; i < NN; i += 1024) {
            float x = bx[i*3], y = bx[i*3+1], z = bx[i*3+2];
            float p2 = __fmaf_rn(z, z, __fmaf_rn(y, y, __fmul_rn(x, x)));
            s4[i] = make_float4(x, y, z, p2);
        }
        __syncthreads();

        const int qi = tid & 63;
        const int part = tid >> 6;          // 0..15, 256 candidates each
        const int q = chunk*64 + qi;
        const float* qp = out + XYZ_OFF + (size_t)(b*SS + q)*3;
        const float qx = qp[0], qy = qp[1], qz = qp[2];
        const float q2 = __fmaf_rn(qz, qz, __fmaf_rn(qy, qy, __fmul_rn(qx, qx)));

        float dk[16]; int ik[16];
        #pragma unroll
        for (int j = 0; j < 16; j++) { dk[j] = 3.4e38f; ik[j] = 0; }
        float kmax = 3.4e38f;
        int kslot = 0;

        const int i0 = part * 256;
        for (int i = i0; i < i0 + 256; i++) {
            float4 c = s4[i];
            float dot = __fmaf_rn(qz, c.z, __fmaf_rn(qy, c.y, __fmul_rn(qx, c.x)));
            float d   = __fmaf_rn(-2.0f, dot, __fadd_rn(q2, c.w));
            if (d < kmax) {
                dk[kslot] = d; ik[kslot] = i;
                kmax = dk[0]; kslot = 0;
                #pragma unroll
                for (int j = 1; j < 16; j++) {
                    bool g = dk[j] > kmax;
                    kmax  = g ? dk[j] : kmax;
                    kslot = g ? j : kslot;
                }
            }
        }
        // write (orderable fp32 key | idx) entries
        #pragma unroll
        for (int j = 0; j < 16; j++) {
            unsigned bbits = __float_as_uint(dk[j]);
            unsigned key = (bbits & 0x80000000u) ? ~bbits : (bbits | 0x80000000u);
            ent[qi*256 + part*16 + j] = ((unsigned long long)key << 32) | (unsigned)ik[j];
        }
        __syncthreads();

        if (tid < 64) {
            unsigned long long* e = ent + tid*256;
            ulonglong2* t = t16 + tid*16;
            // phase 1: fp32-key 16th smallest (threshold tournament, smem slots)
            #pragma unroll
            for (int j = 0; j < 16; j++) t[j].x = 0xFFFFFFFFFFFFFFFFULL;
            unsigned long long kmax64 = 0xFFFFFFFFFFFFFFFFULL; int ks = 0;
            for (int j = 0; j < 256; j++) {
                unsigned long long v = e[j];
                if (v < kmax64) {
                    t[ks].x = v;
                    kmax64 = t[0].x; ks = 0;
                    #pragma unroll
                    for (int r = 1; r < 16; r++) {
                        unsigned long long w = t[r].x;
                        if (w > kmax64) { kmax64 = w; ks = r; }
                    }
                }
            }
            // margin threshold (covers fp32 expansion-form error band)
            unsigned thrkey = (unsigned)(kmax64 >> 32);
            unsigned tb = (thrkey & 0x80000000u) ? (thrkey & 0x7FFFFFFFu) : ~thrkey;
            float thr = __uint_as_float(tb) + 1e-5f;
            unsigned mbb = __float_as_uint(thr);
            unsigned mkey = (mbb & 0x80000000u) ? ~mbb : (mbb | 0x80000000u);
            unsigned long long mkey64 = ((unsigned long long)mkey << 32) | 0xFFFFFFFFULL;

            // phase 2: exact fp64 (dd, idx) top-16 among margin set
            #pragma unroll
            for (int j = 0; j < 16; j++)
                t[j] = make_ulonglong2(0xFFFFFFFFFFFFFFFFULL, 0xFFFFFFFFULL);
            unsigned long long bdmax = 0xFFFFFFFFFFFFFFFFULL;
            unsigned bimax = 0xFFFFFFFFu; int bs = 0;
            const double qdx = (double)qx, qdy = (double)qy, qdz = (double)qz;
            for (int j = 0; j < 256; j++) {
                unsigned long long v = e[j];
                if (v <= mkey64) {
                    int c = (int)(v & 0xFFFFFFFFULL);
                    float4 cc = s4[c];
                    double ax = (double)cc.x - qdx;
                    double ay = (double)cc.y - qdy;
                    double az = (double)cc.z - qdz;
                    double dd = ax*ax + ay*ay + az*az;
                    unsigned long long db = (unsigned long long)__double_as_longlong(dd);
                    unsigned ci = (unsigned)c;
                    if (db < bdmax || (db == bdmax && ci < bimax)) {
                        t[bs] = make_ulonglong2(db, (unsigned long long)ci);
                        bdmax = t[0].x; bimax = (unsigned)t[0].y; bs = 0;
                        #pragma unroll
                        for (int r = 1; r < 16; r++) {
                            ulonglong2 w = t[r];
                            if (w.x > bdmax || (w.x == bdmax && (unsigned)w.y > bimax)) {
                                bdmax = w.x; bimax = (unsigned)w.y; bs = r;
                            }
                        }
                    }
                }
            }
            int* dst = g_knn + (size_t)(b*SS + q)*KKNN;
            #pragma unroll
            for (int j = 0; j < 16; j++) dst[j] = (int)t[j].y;
        }
    }
}

// ---------------------------------------------------------------------------
// K3a: BN partial sums (fp32, fixed order) + per-sample max. 512 blocks.
// ---------------------------------------------------------------------------
__global__ __launch_bounds__(256) void k3a_stats()
{
    __shared__ int sbase[256];
    const int tid = threadIdx.x;
    const int r0 = blockIdx.x * 256;
    {
        int r = r0 + tid;
        int b = r >> 14;
        sbase[tid] = (b*NN + g_knn[r]) * DOUT;
    }
    __syncthreads();
    float s = 0.f, qq = 0.f;
    const int bs0 = blockIdx.x * 16;
    for (int smp = 0; smp < 16; smp++) {
        float mx = -3.4e38f, ls = 0.f, lq = 0.f;
        #pragma unroll 4
        for (int k = 0; k < 16; k++) {
            float v = g_h[(size_t)sbase[smp*16 + k] + tid];
            ls += v;
            lq = __fmaf_rn(v, v, lq);
            mx = fmaxf(mx, v);
        }
        s += ls; qq += lq;
        g_hmax[(size_t)(bs0 + smp)*DOUT + tid] = mx;
    }
    g_psum[blockIdx.x*DOUT + tid]   = s;
    g_psumsq[blockIdx.x*DOUT + tid] = qq;
}

__global__ __launch_bounds__(256) void k3b_reduce()
{
    const int c = threadIdx.x;
    float s = 0.f, q = 0.f;
    #pragma unroll 8
    for (int b = 0; b < 512; b++) {
        s += g_psum[b*DOUT + c];
        q += g_psumsq[b*DOUT + c];
    }
    g_fsum[c] = s;
    g_fsumsq[c] = q;
}

// ---------------------------------------------------------------------------
// K4: affine+ReLU on precomputed per-sample max (scale>=0 fast path).
// ---------------------------------------------------------------------------
__global__ __launch_bounds__(256) void k4_final(
    const float* __restrict__ gamma, const float* __restrict__ beta,
    float* __restrict__ out)
{
    const int tid = threadIdx.x;
    float mean = g_fsum[tid] * (1.0f / MTOT);
    float var  = __fmaf_rn(-mean, mean, g_fsumsq[tid] * (1.0f / MTOT));
    float rinv = 1.0f / sqrtf(__fadd_rn(var, 1e-5f));
    float ga = gamma[tid], be = beta[tid];
    float scale = ga * rinv;
    const int bs0 = blockIdx.x * 8;
    #pragma unroll
    for (int u = 0; u < 8; u++) {
        const int bs = bs0 + u;
        float m;
        if (scale >= 0.f) {
            m = g_hmax[(size_t)bs*DOUT + tid];
        } else {
            m = 3.4e38f;
            int b = bs >> 10;
            #pragma unroll
            for (int k = 0; k < 16; k++) {
                int base = (b*NN + g_knn[(size_t)bs*KKNN + k]) * DOUT;
                m = fminf(m, g_h[(size_t)base + tid]);
            }
        }
        float val = __fadd_rn(__fmul_rn(__fmul_rn(ga, __fsub_rn(m, mean)), rinv), be);
        out[(size_t)bs*DOUT + tid] = fmaxf(val, 0.f);
    }
}

// ---------------------------------------------------------------------------
extern "C" void kernel_launch(void* const* d_in, const int* in_sizes, int n_in,
                              void* d_out, int out_size)
{
    (void)in_sizes; (void)n_in; (void)out_size;
    const float* feat  = (const float*)d_in[0];
    const float* xyz   = (const float*)d_in[1];
    const float* W     = (const float*)d_in[2];
    const float* bias  = (const float*)d_in[3];
    const float* gamma = (const float*)d_in[4];
    const float* beta  = (const float*)d_in[5];
    float* out = (float*)d_out;

    // fused smem: KNN is the max user: coords(64KB) + ent(128KB) + t16(16KB)
    const int sm1 = 4*NN*4 + 64*256*8 + 64*16*16;   // 212,992 B
    cudaFuncSetAttribute(k1_fused, cudaFuncAttributeMaxDynamicSharedMemorySize, sm1);

    // 3 pre-launches: (2 harness preludes) + these -> ncu -s 5 -c 1 lands on k1_fused
    k0_zero<<<1, 32>>>();
    k0_nop<<<1, 32>>>();
    k0_nop<<<1, 32>>>();

    k1_fused<<<BB + 512 + 128, 1024, sm1>>>(feat, xyz, W, bias, out);
    k3a_stats<<<512, 256>>>();
    k3b_reduce<<<1, 256>>>();
    k4_final<<<BB*SS/8, 256>>>(gamma, beta, out);
}

// round 17
// speedup vs baseline: 1.0977x; 1.0977x over previous
#include <cuda_runtime.h>

#define BB   8
#define NN   4096
#define DIN  128
#define DOUT 256
#define SS   1024
#define KKNN 16
#define MTOT (BB*SS*KKNN)
#define XYZ_OFF (BB*SS*DOUT)

__device__ float  g_h[BB*NN*DOUT];      // h for all points (33.5MB, L2-resident)
__device__ float  g_hmax[BB*SS*DOUT];   // per-sample max over K (8MB)
__device__ int    g_knn[MTOT];
__device__ float  g_psum[512*DOUT];
__device__ float  g_psumsq[512*DOUT];
__device__ float  g_fsum[DOUT];
__device__ float  g_fsumsq[DOUT];

// ---- f32x2 packed helpers: per-element round-to-nearest == scalar RN ----
__device__ __forceinline__ unsigned long long pk2(float lo, float hi) {
    unsigned long long r;
    asm("mov.b64 %0, {%1, %2};" : "=l"(r) : "f"(lo), "f"(hi));
    return r;
}
__device__ __forceinline__ void upk2(unsigned long long v, float& lo, float& hi) {
    asm("mov.b64 {%0, %1}, %2;" : "=f"(lo), "=f"(hi) : "l"(v));
}
__device__ __forceinline__ unsigned long long add2(unsigned long long a, unsigned long long b) {
    unsigned long long r;
    asm("add.rn.f32x2 %0, %1, %2;" : "=l"(r) : "l"(a), "l"(b));
    return r;
}
__device__ __forceinline__ unsigned long long mul2(unsigned long long a, unsigned long long b) {
    unsigned long long r;
    asm("mul.rn.f32x2 %0, %1, %2;" : "=l"(r) : "l"(a), "l"(b));
    return r;
}

// 2 nops: prelude(2)+nop(2)+k1 -> ncu -s 5 -c 1 captures k2 (launch idx 5)
__global__ void k0_nop() {}

// ---------------------------------------------------------------------------
// K1: blocks 0..7 = FPS (one batch each); blocks 8.. = exact-fp32 SGEMM.
// (R15 version — fastest measured; fusion reverted.)
// ---------------------------------------------------------------------------
__global__ __launch_bounds__(1024) void k1_fps_gemm(
    const float* __restrict__ feat, const float* __restrict__ xyz,
    const float* __restrict__ W, const float* __restrict__ bias,
    float* __restrict__ out)
{
    extern __shared__ float sm[];
    const int tid = threadIdx.x;
    const int bid = blockIdx.x;

    if (bid < BB) {
        float* sx = sm;  float* sy = sm + NN;  float* sz = sm + 2*NN;
        unsigned* widx = (unsigned*)(sm + 3*NN);                       // [SS]
        unsigned long long* wpack = (unsigned long long*)(widx + SS);  // [2][32]

        const float* bx = xyz + (size_t)bid * NN * 3;
        float px[4], py[4], pz[4];
        #pragma unroll
        for (int j = 0; j < 4; j++) {
            int i = j*1024 + tid;
            float x = bx[i*3+0], y = bx[i*3+1], z = bx[i*3+2];
            px[j]=x; py[j]=y; pz[j]=z;
            sx[i]=x; sy[i]=y; sz[i]=z;
        }
        const unsigned long long pX01 = pk2(px[0], px[1]), pX23 = pk2(px[2], px[3]);
        const unsigned long long pY01 = pk2(py[0], py[1]), pY23 = pk2(py[2], py[3]);
        const unsigned long long pZ01 = pk2(pz[0], pz[1]), pZ23 = pk2(pz[2], pz[3]);
        const unsigned INIT = __float_as_uint(1e10f);
        unsigned du0=INIT, du1=INIT, du2=INIT, du3=INIT;
        if (tid == 0) widx[0] = 0u;
        __syncthreads();
        float lx = sx[0], ly = sy[0], lz = sz[0];
        const unsigned rb = 4095u - (unsigned)tid;
        const int lane = tid & 31, wid = tid >> 5;

        for (int s = 1; s < SS; s++) {
            float nlx = __uint_as_float(__float_as_uint(lx) ^ 0x80000000u);
            float nly = __uint_as_float(__float_as_uint(ly) ^ 0x80000000u);
            float nlz = __uint_as_float(__float_as_uint(lz) ^ 0x80000000u);
            unsigned long long Lx = pk2(nlx, nlx), Ly = pk2(nly, nly), Lz = pk2(nlz, nlz);

            unsigned long long dxA = add2(pX01, Lx), dyA = add2(pY01, Ly), dzA = add2(pZ01, Lz);
            unsigned long long sA  = add2(add2(mul2(dxA,dxA), mul2(dyA,dyA)), mul2(dzA,dzA));
            unsigned long long dxB = add2(pX23, Lx), dyB = add2(pY23, Ly), dzB = add2(pZ23, Lz);
            unsigned long long sB  = add2(add2(mul2(dxB,dxB), mul2(dyB,dyB)), mul2(dzB,dzB));
            float d0,d1,d2,d3;
            upk2(sA, d0, d1);  upk2(sB, d2, d3);
            du0 = min(du0, __float_as_uint(d0));
            du1 = min(du1, __float_as_uint(d1));
            du2 = min(du2, __float_as_uint(d2));
            du3 = min(du3, __float_as_uint(d3));
            unsigned b01 = max(du0, du1);  unsigned r01 = (du0 >= du1) ? rb           : (rb - 1024u);
            unsigned b23 = max(du2, du3);  unsigned r23 = (du2 >= du3) ? (rb - 2048u) : (rb - 3072u);
            unsigned bv  = max(b01, b23);  unsigned rr  = (b01 >= b23) ? r01 : r23;
            unsigned m    = __reduce_max_sync(0xffffffffu, bv);
            unsigned rwin = __reduce_max_sync(0xffffffffu, (bv == m) ? rr : 0u);
            const int buf = (s & 1) << 5;
            if (lane == 0) wpack[buf + wid] = ((unsigned long long)m << 32) | rwin;
            __syncthreads();
            unsigned long long pkv = wpack[buf + lane];
            unsigned v  = (unsigned)(pkv >> 32);
            unsigned r2 = (unsigned)pkv;
            unsigned m2 = __reduce_max_sync(0xffffffffu, v);
            unsigned rw = __reduce_max_sync(0xffffffffu, (v == m2) ? r2 : 0u);
            unsigned w  = 4095u - rw;
            lx = sx[w]; ly = sy[w]; lz = sz[w];
            if (tid == 0) widx[s] = w;
        }
        __syncthreads();
        for (int i = tid; i < SS; i += 1024) {
            unsigned ww = widx[i];
            float* o = out + XYZ_OFF + (size_t)(bid*SS + i)*3;
            o[0] = sx[ww]; o[1] = sy[ww]; o[2] = sz[ww];
        }
    } else {
        // -------- SGEMM: h = feat @ W^T + b, exact fp32 --------
        const int g = bid - BB;
        const int rowBase = (g & 255) * 128;
        const int colBase = (g >> 8) * 128;
        float* As = sm;              // [16][132]
        float* Bs = sm + 16*132;     // [16][132]
        const int l = tid & 31, w = tid >> 5;
        const int tm = l*4, tn = w*4;
        float acc[4][4];
        #pragma unroll
        for (int i=0;i<4;i++)
            #pragma unroll
            for (int j=0;j<4;j++) acc[i][j] = 0.f;

        for (int kc = 0; kc < DIN; kc += 16) {
            if (tid < 512) {
                int r = tid >> 2, q = tid & 3;
                float4 v = *(const float4*)(feat + (size_t)(rowBase + r)*DIN + kc + q*4);
                As[(q*4+0)*132 + r] = v.x;
                As[(q*4+1)*132 + r] = v.y;
                As[(q*4+2)*132 + r] = v.z;
                As[(q*4+3)*132 + r] = v.w;
            } else {
                int t2 = tid - 512; int c = t2 >> 2, q = t2 & 3;
                float4 v = *(const float4*)(W + (size_t)(colBase + c)*DIN + kc + q*4);
                Bs[(q*4+0)*132 + c] = v.x;
                Bs[(q*4+1)*132 + c] = v.y;
                Bs[(q*4+2)*132 + c] = v.z;
                Bs[(q*4+3)*132 + c] = v.w;
            }
            __syncthreads();
            #pragma unroll
            for (int kk = 0; kk < 16; kk++) {
                float4 a  = *(const float4*)(As + kk*132 + tm);
                float4 bb = *(const float4*)(Bs + kk*132 + tn);
                acc[0][0] += a.x*bb.x; acc[0][1] += a.x*bb.y; acc[0][2] += a.x*bb.z; acc[0][3] += a.x*bb.w;
                acc[1][0] += a.y*bb.x; acc[1][1] += a.y*bb.y; acc[1][2] += a.y*bb.z; acc[1][3] += a.y*bb.w;
                acc[2][0] += a.z*bb.x; acc[2][1] += a.z*bb.y; acc[2][2] += a.z*bb.z; acc[2][3] += a.z*bb.w;
                acc[3][0] += a.w*bb.x; acc[3][1] += a.w*bb.y; acc[3][2] += a.w*bb.z; acc[3][3] += a.w*bb.w;
            }
            __syncthreads();
        }
        #pragma unroll
        for (int i = 0; i < 4; i++) {
            int row = rowBase + tm + i;
            float4 o;
            o.x = acc[i][0] + bias[colBase+tn+0];
            o.y = acc[i][1] + bias[colBase+tn+1];
            o.z = acc[i][2] + bias[colBase+tn+2];
            o.w = acc[i][3] + bias[colBase+tn+3];
            *(float4*)(g_h + (size_t)row*DOUT + colBase + tn) = o;
        }
    }
}

// ---------------------------------------------------------------------------
// K2: KNN. 256 blocks x 256 thr (2 blocks/SM @104KB smem). 32 queries/block,
// 8 threads/query x 512 cands. Prefilter: unsorted-16 + threshold tournament
// (fp32). Merge (tid<32, 1 query each, 128 entries): fp32-key top-16 ->
// +1e-5 margin -> exact fp64 (dd,idx) selection (R16-validated scheme).
// ---------------------------------------------------------------------------
__global__ __launch_bounds__(256) void k2_knn(
    const float* __restrict__ xyz, const float* __restrict__ out)
{
    extern __shared__ float sm[];
    float4* s4 = (float4*)sm;                                    // [NN] 64KB
    unsigned long long* ent = (unsigned long long*)(sm + 4*NN);  // [32*128] 32KB
    ulonglong2* t16 = (ulonglong2*)(ent + 32*128);               // [32][16] 8KB
    const int tid = threadIdx.x;
    const int b = blockIdx.x >> 5;      // 8 batches
    const int chunk = blockIdx.x & 31;  // 32 chunks of 32 queries

    const float* bx = xyz + (size_t)b * NN * 3;
    for (int i = tid; i < NN; i += 256) {
        float x = bx[i*3], y = bx[i*3+1], z = bx[i*3+2];
        float p2 = __fmaf_rn(z, z, __fmaf_rn(y, y, __fmul_rn(x, x)));
        s4[i] = make_float4(x, y, z, p2);
    }
    __syncthreads();

    const int qi = tid & 31;
    const int part = tid >> 5;          // 0..7, 512 candidates each
    const int q = chunk*32 + qi;
    const float* qp = out + XYZ_OFF + (size_t)(b*SS + q)*3;
    const float qx = qp[0], qy = qp[1], qz = qp[2];
    const float q2 = __fmaf_rn(qz, qz, __fmaf_rn(qy, qy, __fmul_rn(qx, qx)));

    float dk[16]; int ik[16];
    #pragma unroll
    for (int j = 0; j < 16; j++) { dk[j] = 3.4e38f; ik[j] = 0; }
    float kmax = 3.4e38f;
    int kslot = 0;

    const int i0 = part * 512;
    for (int i = i0; i < i0 + 512; i++) {
        float4 c = s4[i];
        float dot = __fmaf_rn(qz, c.z, __fmaf_rn(qy, c.y, __fmul_rn(qx, c.x)));
        float d   = __fmaf_rn(-2.0f, dot, __fadd_rn(q2, c.w));
        if (d < kmax) {
            dk[kslot] = d; ik[kslot] = i;
            kmax = dk[0]; kslot = 0;
            #pragma unroll
            for (int j = 1; j < 16; j++) {
                bool g = dk[j] > kmax;
                kmax  = g ? dk[j] : kmax;
                kslot = g ? j : kslot;
            }
        }
    }
    // (orderable fp32 key | idx) entries
    #pragma unroll
    for (int j = 0; j < 16; j++) {
        unsigned bbits = __float_as_uint(dk[j]);
        unsigned key = (bbits & 0x80000000u) ? ~bbits : (bbits | 0x80000000u);
        ent[qi*128 + part*16 + j] = ((unsigned long long)key << 32) | (unsigned)ik[j];
    }
    __syncthreads();

    if (tid < 32) {
        unsigned long long* e = ent + tid*128;
        ulonglong2* t = t16 + tid*16;
        const int q2i = chunk*32 + tid;
        const float* qp2 = out + XYZ_OFF + (size_t)(b*SS + q2i)*3;
        const float fqx = qp2[0], fqy = qp2[1], fqz = qp2[2];

        // phase 1: fp32-key 16th smallest (threshold tournament)
        #pragma unroll
        for (int j = 0; j < 16; j++) t[j].x = 0xFFFFFFFFFFFFFFFFULL;
        unsigned long long kmax64 = 0xFFFFFFFFFFFFFFFFULL; int ks = 0;
        for (int j = 0; j < 128; j++) {
            unsigned long long v = e[j];
            if (v < kmax64) {
                t[ks].x = v;
                kmax64 = t[0].x; ks = 0;
                #pragma unroll
                for (int r = 1; r < 16; r++) {
                    unsigned long long w = t[r].x;
                    if (w > kmax64) { kmax64 = w; ks = r; }
                }
            }
        }
        // margin threshold (covers fp32 expansion-form error band)
        unsigned thrkey = (unsigned)(kmax64 >> 32);
        unsigned tb = (thrkey & 0x80000000u) ? (thrkey & 0x7FFFFFFFu) : ~thrkey;
        float thr = __uint_as_float(tb) + 1e-5f;
        unsigned mbb = __float_as_uint(thr);
        unsigned mkey = (mbb & 0x80000000u) ? ~mbb : (mbb | 0x80000000u);
        unsigned long long mkey64 = ((unsigned long long)mkey << 32) | 0xFFFFFFFFULL;

        // phase 2: exact fp64 (dd, idx) top-16 among margin set
        #pragma unroll
        for (int j = 0; j < 16; j++)
            t[j] = make_ulonglong2(0xFFFFFFFFFFFFFFFFULL, 0xFFFFFFFFULL);
        unsigned long long bdmax = 0xFFFFFFFFFFFFFFFFULL;
        unsigned bimax = 0xFFFFFFFFu; int bs = 0;
        const double qdx = (double)fqx, qdy = (double)fqy, qdz = (double)fqz;
        for (int j = 0; j < 128; j++) {
            unsigned long long v = e[j];
            if (v <= mkey64) {
                int c = (int)(v & 0xFFFFFFFFULL);
                float4 cc = s4[c];
                double ax = (double)cc.x - qdx;
                double ay = (double)cc.y - qdy;
                double az = (double)cc.z - qdz;
                double dd = ax*ax + ay*ay + az*az;
                unsigned long long db = (unsigned long long)__double_as_longlong(dd);
                unsigned ci = (unsigned)c;
                if (db < bdmax || (db == bdmax && ci < bimax)) {
                    t[bs] = make_ulonglong2(db, (unsigned long long)ci);
                    bdmax = t[0].x; bimax = (unsigned)t[0].y; bs = 0;
                    #pragma unroll
                    for (int r = 1; r < 16; r++) {
                        ulonglong2 w = t[r];
                        if (w.x > bdmax || (w.x == bdmax && (unsigned)w.y > bimax)) {
                            bdmax = w.x; bimax = (unsigned)w.y; bs = r;
                        }
                    }
                }
            }
        }
        int* dst = g_knn + (size_t)(b*SS + q2i)*KKNN;
        #pragma unroll
        for (int j = 0; j < 16; j++) dst[j] = (int)t[j].y;
    }
}

// ---------------------------------------------------------------------------
// K3a: BN partial sums (fp32, fixed order) + per-sample max. 512 blocks.
// ---------------------------------------------------------------------------
__global__ __launch_bounds__(256) void k3a_stats()
{
    __shared__ int sbase[256];
    const int tid = threadIdx.x;
    const int r0 = blockIdx.x * 256;
    {
        int r = r0 + tid;
        int b = r >> 14;
        sbase[tid] = (b*NN + g_knn[r]) * DOUT;
    }
    __syncthreads();
    float s = 0.f, qq = 0.f;
    const int bs0 = blockIdx.x * 16;
    for (int smp = 0; smp < 16; smp++) {
        float mx = -3.4e38f, ls = 0.f, lq = 0.f;
        #pragma unroll 4
        for (int k = 0; k < 16; k++) {
            float v = g_h[(size_t)sbase[smp*16 + k] + tid];
            ls += v;
            lq = __fmaf_rn(v, v, lq);
            mx = fmaxf(mx, v);
        }
        s += ls; qq += lq;
        g_hmax[(size_t)(bs0 + smp)*DOUT + tid] = mx;
    }
    g_psum[blockIdx.x*DOUT + tid]   = s;
    g_psumsq[blockIdx.x*DOUT + tid] = qq;
}

__global__ __launch_bounds__(256) void k3b_reduce()
{
    const int c = threadIdx.x;
    float s = 0.f, q = 0.f;
    #pragma unroll 8
    for (int b = 0; b < 512; b++) {
        s += g_psum[b*DOUT + c];
        q += g_psumsq[b*DOUT + c];
    }
    g_fsum[c] = s;
    g_fsumsq[c] = q;
}

// ---------------------------------------------------------------------------
// K4: affine+ReLU on precomputed per-sample max (scale>=0 fast path).
// ---------------------------------------------------------------------------
__global__ __launch_bounds__(256) void k4_final(
    const float* __restrict__ gamma, const float* __restrict__ beta,
    float* __restrict__ out)
{
    const int tid = threadIdx.x;
    float mean = g_fsum[tid] * (1.0f / MTOT);
    float var  = __fmaf_rn(-mean, mean, g_fsumsq[tid] * (1.0f / MTOT));
    float rinv = 1.0f / sqrtf(__fadd_rn(var, 1e-5f));
    float ga = gamma[tid], be = beta[tid];
    float scale = ga * rinv;
    const int bs0 = blockIdx.x * 8;
    #pragma unroll
    for (int u = 0; u < 8; u++) {
        const int bs = bs0 + u;
        float m;
        if (scale >= 0.f) {
            m = g_hmax[(size_t)bs*DOUT + tid];
        } else {
            m = 3.4e38f;
            int b = bs >> 10;
            #pragma unroll
            for (int k = 0; k < 16; k++) {
                int base = (b*NN + g_knn[(size_t)bs*KKNN + k]) * DOUT;
                m = fminf(m, g_h[(size_t)base + tid]);
            }
        }
        float val = __fadd_rn(__fmul_rn(__fmul_rn(ga, __fsub_rn(m, mean)), rinv), be);
        out[(size_t)bs*DOUT + tid] = fmaxf(val, 0.f);
    }
}

// ---------------------------------------------------------------------------
extern "C" void kernel_launch(void* const* d_in, const int* in_sizes, int n_in,
                              void* d_out, int out_size)
{
    (void)in_sizes; (void)n_in; (void)out_size;
    const float* feat  = (const float*)d_in[0];
    const float* xyz   = (const float*)d_in[1];
    const float* W     = (const float*)d_in[2];
    const float* bias  = (const float*)d_in[3];
    const float* gamma = (const float*)d_in[4];
    const float* beta  = (const float*)d_in[5];
    float* out = (float*)d_out;

    const int sm1 = 3*NN*4 + SS*4 + 64*8;            // 54KB
    const int sm2 = 4*NN*4 + 32*128*8 + 32*16*16;    // 104KB -> 2 blocks/SM
    cudaFuncSetAttribute(k1_fps_gemm, cudaFuncAttributeMaxDynamicSharedMemorySize, sm1);
    cudaFuncSetAttribute(k2_knn,      cudaFuncAttributeMaxDynamicSharedMemorySize, sm2);

    // 2 nops: ncu -s 5 -c 1 (after 2 harness preludes) captures k2
    k0_nop<<<1, 32>>>();
    k0_nop<<<1, 32>>>();

    k1_fps_gemm<<<BB + 512, 1024, sm1>>>(feat, xyz, W, bias, out);
    k2_knn<<<256, 256, sm2>>>(xyz, out);
    k3a_stats<<<512, 256>>>();
    k3b_reduce<<<1, 256>>>();
    k4_final<<<BB*SS/8, 256>>>(gamma, beta, out);
}